// round 9
// baseline (speedup 1.0000x reference)
#include <cuda_runtime.h>
#include <math_constants.h>
#include <stdint.h>

#define BATCH   2
#define CNUM    81
#define NCLS    (CNUM - 1)
#define NP      CNUM
#define RMAX    1024
#define VMAX    256
#define NMS_THR 0.3f
#define NBLK    (NCLS * BATCH)   // 160
#define NT      256

__device__ float    g_dets[BATCH][NCLS][NP][5];
__device__ int      g_cnt[BATCH][NCLS];
__device__ unsigned long long g_list[BATCH][NCLS][RMAX];  // compacted key<<32|r
__device__ int      g_vcnt[BATCH][NCLS];                  // reset by owner CTA each launch
__device__ unsigned int g_done  = 0;    // combine-phase counter (self-resetting)
__device__ unsigned int g_arrive = 0;   // barrier arrive counter (self-resetting)
__device__ unsigned int g_phase  = 0;   // monotone phase counter (never reset)

__global__ void __launch_bounds__(NT)
fused_kernel(const float* __restrict__ cls_prob,   // (B,R,C)
             const float* __restrict__ rois,       // (B,R,5)
             const float* __restrict__ bbox_pred,  // (B,R,4C)
             const float* __restrict__ im_info,    // (B,3)
             const float* __restrict__ thr,        // (C,)
             float* __restrict__ out, int out_size,
             int R)
{
    const int c    = blockIdx.x + 1;   // this CTA's class for phase 1
    const int b    = blockIdx.y;
    const int tid  = threadIdx.x;
    const int cta  = blockIdx.y * gridDim.x + blockIdx.x;

    __shared__ unsigned long long ukey[RMAX];
    __shared__ float sx1[RMAX], sy1[RMAX], sx2[RMAX], sy2[RMAX], sar[RMAX];
    __shared__ unsigned long long sup[VMAX][4];
    __shared__ unsigned long long keptw[4];
    __shared__ unsigned char keep[RMAX];           // fallback only
    __shared__ int sV;

    // ================= phase 0: coalesced scan + global compaction =========
    {
        const int total  = BATCH * R * CNUM;       // 162000
        const int stride = NBLK * NT;              // 40960
        for (int e = cta * NT + tid; e < total; e += stride) {
            const float v = cls_prob[e];
            const int cc  = e % CNUM;
            if (cc == 0) continue;
            if (v > __ldg(&thr[cc])) {
                const int br = e / CNUM;           // b*R + r
                const int bb = br / R;
                const int r  = br - bb * R;
                const uint32_t key = ~(__float_as_uint(v) ^ 0x80000000u);
                const int pos = atomicAdd(&g_vcnt[bb][cc - 1], 1);
                g_list[bb][cc - 1][pos] = ((unsigned long long)key << 32) | (uint32_t)r;
            }
        }
    }

    // ================= grid barrier (self-resetting, phase-counter) =========
    __syncthreads();
    __threadfence();
    if (tid == 0) {
        const unsigned ph = atomicAdd(&g_phase, 0u);      // read current phase
        const unsigned old = atomicAdd(&g_arrive, 1u);
        if (old == NBLK - 1u) {
            atomicExch(&g_arrive, 0u);                    // reset for next launch
            __threadfence();
            atomicAdd(&g_phase, 1u);                      // release
        } else {
            while (atomicAdd(&g_phase, 0u) == ph) __nanosleep(64);
        }
    }
    __syncthreads();
    __threadfence();

    // ================= phase 1: per-(b,c) NMS ==============================
    if (tid == 0) {
        sV = g_vcnt[b][c - 1];
        g_vcnt[b][c - 1] = 0;                             // reset for next replay
    }
    __syncthreads();
    const int V = sV;

    // load compacted keys (V small, one coalesced round)
    for (int i = tid; i < V; i += NT) ukey[i] = g_list[b][c - 1][i];
    __syncthreads();

    const float h_im = im_info[b * 3 + 0];
    const float w_im = im_info[b * 3 + 1];

    // ---- fused decode + rank + scatter ----
    for (int p = tid; p < V; p += NT) {
        const unsigned long long kp = ukey[p];
        const int r = (int)(uint32_t)kp;

        const float* roi = rois + (size_t)(b * R + r) * 5;
        const float x1 = roi[1], y1 = roi[2], x2 = roi[3], y2 = roi[4];
        const float4 d4 = *(const float4*)(bbox_pred + ((size_t)(b * R + r) * CNUM + c) * 4);

        int rank = 0;
        for (int j = 0; j < V; ++j)
            rank += (ukey[j] < kp);

        const float w  = x2 - x1 + 1.0f;
        const float h  = y2 - y1 + 1.0f;
        const float cx = x1 + 0.5f * w;
        const float cy = y1 + 0.5f * h;
        const float pcx = d4.x * 0.1f * w + cx;
        const float pcy = d4.y * 0.1f * h + cy;
        const float pw  = expf(d4.z * 0.2f) * w;
        const float ph  = expf(d4.w * 0.2f) * h;

        float nx1 = pcx - 0.5f * pw;
        float ny1 = pcy - 0.5f * ph;
        float nx2 = pcx + 0.5f * pw;
        float ny2 = pcy + 0.5f * ph;
        nx1 = fminf(fmaxf(nx1, 0.0f), w_im - 1.0f);
        nx2 = fminf(fmaxf(nx2, 0.0f), w_im - 1.0f);
        ny1 = fminf(fmaxf(ny1, 0.0f), h_im - 1.0f);
        ny2 = fminf(fmaxf(ny2, 0.0f), h_im - 1.0f);

        sx1[rank] = nx1; sy1[rank] = ny1; sx2[rank] = nx2; sy2[rank] = ny2;
        sar[rank] = fmaxf(nx2 - nx1, 0.0f) * fmaxf(ny2 - ny1, 0.0f);
    }
    __syncthreads();

    if (V <= VMAX) {
        // ---- matrix NMS mask build ----
        const int W = (V + 63) >> 6;
        for (int t = tid; t < V * W; t += NT) {
            const int i = t / W;
            const int w = t - i * W;
            const float ax1 = sx1[i], ay1 = sy1[i];
            const float ax2 = sx2[i], ay2 = sy2[i];
            const float aa  = sar[i];
            unsigned long long bits = 0ULL;
            const int j0 = max(i + 1, w << 6);
            const int j1 = min(V, (w + 1) << 6);
            for (int j = j0; j < j1; ++j) {
                const float xx1 = fmaxf(ax1, sx1[j]);
                const float yy1 = fmaxf(ay1, sy1[j]);
                const float xx2 = fminf(ax2, sx2[j]);
                const float yy2 = fminf(ay2, sy2[j]);
                const float inter = fmaxf(xx2 - xx1, 0.0f) * fmaxf(yy2 - yy1, 0.0f);
                const float iou = inter / (aa + sar[j] - inter + 1e-9f);
                if (iou > NMS_THR) bits |= 1ULL << (j & 63);
            }
            sup[i][w] = bits;
        }
        __syncthreads();

        // ---- thread-0 register-word greedy: kept bitmask only ----
        if (tid == 0) {
            const int W2 = (V + 63) >> 6;
            auto wordinit = [&](int w) -> unsigned long long {
                const int lo = w << 6;
                if (V >= lo + 64) return ~0ULL;
                if (V <= lo)      return 0ULL;
                return (1ULL << (V - lo)) - 1ULL;
            };
            unsigned long long r0 = wordinit(0), r1 = wordinit(1);
            unsigned long long r2 = wordinit(2), r3 = wordinit(3);
            unsigned long long k0 = 0, k1 = 0, k2 = 0, k3 = 0;
            int k = 0;
            for (;;) {
                int i;
                if (r0)      { const int t = __ffsll((long long)r0) - 1; r0 &= ~(1ULL << t); k0 |= 1ULL << t; i = t; }
                else if (r1) { const int t = __ffsll((long long)r1) - 1; r1 &= ~(1ULL << t); k1 |= 1ULL << t; i = 64 + t; }
                else if (r2) { const int t = __ffsll((long long)r2) - 1; r2 &= ~(1ULL << t); k2 |= 1ULL << t; i = 128 + t; }
                else if (r3) { const int t = __ffsll((long long)r3) - 1; r3 &= ~(1ULL << t); k3 |= 1ULL << t; i = 192 + t; }
                else break;
                r0 &= ~sup[i][0];
                if (W2 > 1) r1 &= ~sup[i][1];
                if (W2 > 2) r2 &= ~sup[i][2];
                if (W2 > 3) r3 &= ~sup[i][3];
                ++k;
            }
            keptw[0] = k0; keptw[1] = k1; keptw[2] = k2; keptw[3] = k3;
            g_cnt[b][c - 1] = k;
        }
        __syncthreads();

        // ---- parallel store of kept dets ----
        for (int i = tid; i < V; i += NT) {
            const int w = i >> 6;
            const unsigned long long word = keptw[w];
            if ((word >> (i & 63)) & 1ULL) {
                int k = __popcll(word & ((1ULL << (i & 63)) - 1ULL));
                for (int q = 0; q < w; ++q) k += __popcll(keptw[q]);
                if (k < NP) {
                    g_dets[b][c - 1][k][0] = sx1[i];
                    g_dets[b][c - 1][k][1] = sy1[i];
                    g_dets[b][c - 1][k][2] = sx2[i];
                    g_dets[b][c - 1][k][3] = sy2[i];
                    g_dets[b][c - 1][k][4] = (float)c;
                }
            }
        }
    } else {
        // ---- fallback: barrier-loop greedy NMS (rarely taken) ----
        for (int i = tid; i < V; i += NT) keep[i] = 1;
        __syncthreads();
        for (int i = 0; i < V; ++i) {
            if (keep[i]) {
                const float ax1 = sx1[i], ay1 = sy1[i];
                const float ax2 = sx2[i], ay2 = sy2[i];
                const float aa  = sar[i];
                for (int j = i + 1 + tid; j < V; j += NT) {
                    if (keep[j]) {
                        const float xx1 = fmaxf(ax1, sx1[j]);
                        const float yy1 = fmaxf(ay1, sy1[j]);
                        const float xx2 = fminf(ax2, sx2[j]);
                        const float yy2 = fminf(ay2, sy2[j]);
                        const float inter = fmaxf(xx2 - xx1, 0.0f) * fmaxf(yy2 - yy1, 0.0f);
                        const float iou = inter / (aa + sar[j] - inter + 1e-9f);
                        if (iou > NMS_THR) keep[j] = 0;
                    }
                }
            }
            __syncthreads();
        }
        if (tid == 0) {
            int k = 0;
            for (int i = 0; i < V; ++i) {
                if (keep[i]) {
                    if (k < NP) {
                        g_dets[b][c - 1][k][0] = sx1[i];
                        g_dets[b][c - 1][k][1] = sy1[i];
                        g_dets[b][c - 1][k][2] = sx2[i];
                        g_dets[b][c - 1][k][3] = sy2[i];
                        g_dets[b][c - 1][k][4] = (float)c;
                    }
                    ++k;
                }
            }
            g_cnt[b][c - 1] = k;
        }
    }

    // ======== last-block-done combine ========
    __threadfence();
    __syncthreads();

    __shared__ unsigned int is_last;
    if (tid == 0) is_last = (atomicAdd(&g_done, 1u) == NBLK - 1u) ? 1u : 0u;
    __syncthreads();
    if (!is_last) return;

    __shared__ int cnts[BATCH][NCLS];
    __shared__ int incl[BATCH][NCLS];

    for (int t = tid; t < BATCH * NCLS; t += NT)
        cnts[t / NCLS][t % NCLS] = g_cnt[t / NCLS][t % NCLS];
    __syncthreads();

    if (tid < 64) {
        const int w = tid >> 5;
        const int l = tid & 31;
        int carry = 0;
        #pragma unroll
        for (int ch = 0; ch < 3; ++ch) {
            const int cc = ch * 32 + l;
            int v = (cc < NCLS) ? cnts[w][cc] : 0;
            #pragma unroll
            for (int off = 1; off < 32; off <<= 1) {
                const int n_ = __shfl_up_sync(0xffffffffu, v, off);
                if (l >= off) v += n_;
            }
            if (cc < NCLS) incl[w][cc] = v + carry;
            carry += __shfl_sync(0xffffffffu, v, 31);
        }
    }

    for (int i = tid; i < BATCH * NP * 5; i += NT) out[i] = 0.0f;
    __syncthreads();

    for (int t = tid; t < BATCH * NP; t += NT) {
        const int bb = t / NP;
        const int k  = t - bb * NP;
        const int total = incl[bb][NCLS - 1];
        const int n = total < NP ? total : NP;
        if (k < n) {
            int lo = 0, hi = NCLS - 1;
            while (lo < hi) {
                const int mid = (lo + hi) >> 1;
                if (incl[bb][mid] > k) hi = mid; else lo = mid + 1;
            }
            const int cc = lo;
            const int tt = k - (incl[bb][cc] - cnts[bb][cc]);
            float* gout = out + (size_t)bb * NP * 5 + (size_t)k * 5;
            #pragma unroll
            for (int q = 0; q < 5; ++q) gout[q] = g_dets[bb][cc][tt][q];
        }
        if (k == 0 && out_size >= BATCH * NP * 5 + BATCH)
            out[BATCH * NP * 5 + bb] = (float)n;
    }

    const int base = BATCH * NP * 5 + BATCH;
    for (int i = base + tid; i < out_size; i += NT) out[i] = 0.0f;

    __syncthreads();
    if (tid == 0) g_done = 0;   // reset for next graph replay
}

extern "C" void kernel_launch(void* const* d_in, const int* in_sizes, int n_in,
                              void* d_out, int out_size)
{
    const float* cls_prob  = (const float*)d_in[0];
    const float* rois      = (const float*)d_in[1];
    const float* bbox_pred = (const float*)d_in[2];
    const float* im_info   = (const float*)d_in[3];
    const float* thr       = (const float*)d_in[4];
    float* out = (float*)d_out;

    const int R = in_sizes[0] / (BATCH * CNUM);      // 1000

    dim3 grid(NCLS, BATCH);
    fused_kernel<<<grid, NT>>>(cls_prob, rois, bbox_pred, im_info, thr,
                               out, out_size, R);
}

// round 10
// speedup vs baseline: 1.5165x; 1.5165x over previous
#include <cuda_runtime.h>
#include <math_constants.h>
#include <stdint.h>

#define BATCH   2
#define CNUM    81
#define NCLS    (CNUM - 1)
#define NP      CNUM
#define VCAP    512          // storage cap per chain (V never near this)
#define VMAX    128          // fast-path cap for matrix NMS
#define NMS_THR 0.3f
#define NT      512          // threads per CTA (2 chains x 256)
#define HT      256          // threads per chain
#define RPT     4            // hoisted scores per thread (HT*4 = 1024 >= R)
#define NBLK    (NCLS / 2 * BATCH)   // 80 CTAs

__device__ float g_dets[BATCH][NCLS][NP][5];
__device__ int   g_cnt[BATCH][NCLS];
__device__ unsigned int g_done = 0;

// named barrier for one 256-thread chain (id 1 or 2)
#define CHAIN_SYNC(h) asm volatile("bar.sync %0, %1;" :: "r"((h) + 1), "r"(HT) : "memory")

__global__ void __launch_bounds__(NT)
fused_kernel(const float* __restrict__ cls_prob,   // (B,R,C)
             const float* __restrict__ rois,       // (B,R,5)
             const float* __restrict__ bbox_pred,  // (B,R,4C)
             const float* __restrict__ im_info,    // (B,3)
             const float* __restrict__ thr,        // (C,)
             float* __restrict__ out, int out_size,
             int R)
{
    const int tid  = threadIdx.x;
    const int h    = tid >> 8;          // chain (0/1)
    const int lt   = tid & (HT - 1);    // lane within chain
    const int lane = tid & 31;
    const int b    = blockIdx.y;
    const int cls  = blockIdx.x * 2 + h;   // 0..79
    const int c    = cls + 1;              // class id 1..80

    __shared__ unsigned long long ukey[2][VCAP];
    __shared__ float sx1[2][VCAP], sy1[2][VCAP], sx2[2][VCAP], sy2[2][VCAP], sar[2][VCAP];
    __shared__ unsigned long long sup[2][VMAX][2];
    __shared__ unsigned long long keptw[2][2];
    __shared__ unsigned char keep[2][VCAP];       // fallback only
    __shared__ int svcnt[2];
    __shared__ unsigned int is_last;
    __shared__ int cnts[BATCH][NCLS];
    __shared__ int incl[BATCH][NCLS];

    if (lt == 0) svcnt[h] = 0;
    CHAIN_SYNC(h);

    const float h_im = im_info[b * 3 + 0];
    const float w_im = im_info[b * 3 + 1];
    const float th   = thr[c];

    // ---- pass 1: hoisted score loads + warp-aggregated compaction ----
    float sc[RPT];
    #pragma unroll
    for (int it = 0; it < RPT; ++it) {
        const int rr = lt + it * HT;
        sc[it] = (rr < R) ? cls_prob[(size_t)(b * R + rr) * CNUM + c] : -1.0f;
    }
    #pragma unroll
    for (int it = 0; it < RPT; ++it) {
        const int rr = lt + it * HT;
        const bool valid = sc[it] > th;
        const unsigned mask = __ballot_sync(0xffffffffu, valid);
        if (mask) {
            const int leader = __ffs(mask) - 1;
            int base = 0;
            if (lane == leader) base = atomicAdd(&svcnt[h], __popc(mask));
            base = __shfl_sync(0xffffffffu, base, leader);
            if (valid) {
                const int pos = base + __popc(mask & ((1u << lane) - 1u));
                if (pos < VCAP) {
                    const uint32_t ub = __float_as_uint(sc[it]) ^ 0x80000000u;
                    ukey[h][pos] = ((unsigned long long)(~ub) << 32) | (uint32_t)rr;
                }
            }
        }
    }
    CHAIN_SYNC(h);

    const int V = min(svcnt[h], VCAP);

    // ---- fused decode + rank + scatter ----
    for (int p = lt; p < V; p += HT) {
        const unsigned long long kp = ukey[h][p];
        const int r = (int)(uint32_t)kp;

        const float* roi = rois + (size_t)(b * R + r) * 5;
        const float x1 = roi[1], y1 = roi[2], x2 = roi[3], y2 = roi[4];
        const float4 d4 = *(const float4*)(bbox_pred + ((size_t)(b * R + r) * CNUM + c) * 4);

        int rank = 0;
        for (int j = 0; j < V; ++j)
            rank += (ukey[h][j] < kp);

        const float w  = x2 - x1 + 1.0f;
        const float hh = y2 - y1 + 1.0f;
        const float cx = x1 + 0.5f * w;
        const float cy = y1 + 0.5f * hh;
        const float pcx = d4.x * 0.1f * w + cx;
        const float pcy = d4.y * 0.1f * hh + cy;
        const float pw  = expf(d4.z * 0.2f) * w;
        const float ph  = expf(d4.w * 0.2f) * hh;

        float nx1 = pcx - 0.5f * pw;
        float ny1 = pcy - 0.5f * ph;
        float nx2 = pcx + 0.5f * pw;
        float ny2 = pcy + 0.5f * ph;
        nx1 = fminf(fmaxf(nx1, 0.0f), w_im - 1.0f);
        nx2 = fminf(fmaxf(nx2, 0.0f), w_im - 1.0f);
        ny1 = fminf(fmaxf(ny1, 0.0f), h_im - 1.0f);
        ny2 = fminf(fmaxf(ny2, 0.0f), h_im - 1.0f);

        sx1[h][rank] = nx1; sy1[h][rank] = ny1;
        sx2[h][rank] = nx2; sy2[h][rank] = ny2;
        sar[h][rank] = fmaxf(nx2 - nx1, 0.0f) * fmaxf(ny2 - ny1, 0.0f);
    }
    CHAIN_SYNC(h);

    if (V <= VMAX) {
        // ---- matrix NMS mask build (W <= 2 words/row) ----
        const int W = (V + 63) >> 6;
        for (int t = lt; t < V * W; t += HT) {
            const int i = t / W;
            const int w = t - i * W;
            const float ax1 = sx1[h][i], ay1 = sy1[h][i];
            const float ax2 = sx2[h][i], ay2 = sy2[h][i];
            const float aa  = sar[h][i];
            unsigned long long bits = 0ULL;
            const int j0 = max(i + 1, w << 6);
            const int j1 = min(V, (w + 1) << 6);
            for (int j = j0; j < j1; ++j) {
                const float xx1 = fmaxf(ax1, sx1[h][j]);
                const float yy1 = fmaxf(ay1, sy1[h][j]);
                const float xx2 = fminf(ax2, sx2[h][j]);
                const float yy2 = fminf(ay2, sy2[h][j]);
                const float inter = fmaxf(xx2 - xx1, 0.0f) * fmaxf(yy2 - yy1, 0.0f);
                const float iou = inter / (aa + sar[h][j] - inter + 1e-9f);
                if (iou > NMS_THR) bits |= 1ULL << (j & 63);
            }
            sup[h][i][w] = bits;
        }
        CHAIN_SYNC(h);

        // ---- chain-leader register-word greedy: kept bitmask only ----
        if (lt == 0) {
            unsigned long long r0 = 0, r1 = 0;
            if (V >= 64) { r0 = ~0ULL; r1 = (V >= 128) ? ~0ULL : ((V > 64) ? ((1ULL << (V - 64)) - 1ULL) : 0ULL); }
            else if (V > 0) r0 = (1ULL << V) - 1ULL;
            unsigned long long k0 = 0, k1 = 0;
            int k = 0;
            for (;;) {
                int i;
                if (r0)      { const int t = __ffsll((long long)r0) - 1; r0 &= ~(1ULL << t); k0 |= 1ULL << t; i = t; }
                else if (r1) { const int t = __ffsll((long long)r1) - 1; r1 &= ~(1ULL << t); k1 |= 1ULL << t; i = 64 + t; }
                else break;
                r0 &= ~sup[h][i][0];
                if (V > 64) r1 &= ~sup[h][i][1];
                ++k;
            }
            keptw[h][0] = k0; keptw[h][1] = k1;
            g_cnt[b][cls] = k;
        }
        CHAIN_SYNC(h);

        // ---- parallel store of kept dets ----
        for (int i = lt; i < V; i += HT) {
            const int w = i >> 6;
            const unsigned long long word = keptw[h][w];
            if ((word >> (i & 63)) & 1ULL) {
                int k = __popcll(word & ((1ULL << (i & 63)) - 1ULL));
                if (w) k += __popcll(keptw[h][0]);
                if (k < NP) {
                    g_dets[b][cls][k][0] = sx1[h][i];
                    g_dets[b][cls][k][1] = sy1[h][i];
                    g_dets[b][cls][k][2] = sx2[h][i];
                    g_dets[b][cls][k][3] = sy2[h][i];
                    g_dets[b][cls][k][4] = (float)c;
                }
            }
        }
    } else {
        // ---- fallback: barrier-loop greedy NMS (rarely taken) ----
        for (int i = lt; i < V; i += HT) keep[h][i] = 1;
        CHAIN_SYNC(h);
        for (int i = 0; i < V; ++i) {
            if (keep[h][i]) {
                const float ax1 = sx1[h][i], ay1 = sy1[h][i];
                const float ax2 = sx2[h][i], ay2 = sy2[h][i];
                const float aa  = sar[h][i];
                for (int j = i + 1 + lt; j < V; j += HT) {
                    if (keep[h][j]) {
                        const float xx1 = fmaxf(ax1, sx1[h][j]);
                        const float yy1 = fmaxf(ay1, sy1[h][j]);
                        const float xx2 = fminf(ax2, sx2[h][j]);
                        const float yy2 = fminf(ay2, sy2[h][j]);
                        const float inter = fmaxf(xx2 - xx1, 0.0f) * fmaxf(yy2 - yy1, 0.0f);
                        const float iou = inter / (aa + sar[h][j] - inter + 1e-9f);
                        if (iou > NMS_THR) keep[h][j] = 0;
                    }
                }
            }
            CHAIN_SYNC(h);
        }
        if (lt == 0) {
            int k = 0;
            for (int i = 0; i < V; ++i) {
                if (keep[h][i]) {
                    if (k < NP) {
                        g_dets[b][cls][k][0] = sx1[h][i];
                        g_dets[b][cls][k][1] = sy1[h][i];
                        g_dets[b][cls][k][2] = sx2[h][i];
                        g_dets[b][cls][k][3] = sy2[h][i];
                        g_dets[b][cls][k][4] = (float)c;
                    }
                    ++k;
                }
            }
            g_cnt[b][cls] = k;
        }
    }

    // ======== last-block-done combine (whole CTA) ========
    __threadfence();
    __syncthreads();

    if (tid == 0) is_last = (atomicAdd(&g_done, 1u) == NBLK - 1u) ? 1u : 0u;
    __syncthreads();
    if (!is_last) return;

    for (int t = tid; t < BATCH * NCLS; t += NT)
        cnts[t / NCLS][t % NCLS] = g_cnt[t / NCLS][t % NCLS];
    __syncthreads();

    // per-image inclusive prefix via chunked warp scans
    if (tid < 64) {
        const int w = tid >> 5;     // image
        const int l = tid & 31;
        int carry = 0;
        #pragma unroll
        for (int ch = 0; ch < 3; ++ch) {
            const int cc = ch * 32 + l;
            int v = (cc < NCLS) ? cnts[w][cc] : 0;
            #pragma unroll
            for (int off = 1; off < 32; off <<= 1) {
                const int n_ = __shfl_up_sync(0xffffffffu, v, off);
                if (l >= off) v += n_;
            }
            if (cc < NCLS) incl[w][cc] = v + carry;
            carry += __shfl_sync(0xffffffffu, v, 31);
        }
    }

    for (int i = tid; i < BATCH * NP * 5; i += NT) out[i] = 0.0f;
    __syncthreads();

    for (int t = tid; t < BATCH * NP; t += NT) {
        const int bb = t / NP;
        const int k  = t - bb * NP;
        const int total = incl[bb][NCLS - 1];
        const int n = total < NP ? total : NP;
        if (k < n) {
            int lo = 0, hi = NCLS - 1;
            while (lo < hi) {
                const int mid = (lo + hi) >> 1;
                if (incl[bb][mid] > k) hi = mid; else lo = mid + 1;
            }
            const int cc = lo;
            const int tt = k - (incl[bb][cc] - cnts[bb][cc]);
            float* gout = out + (size_t)bb * NP * 5 + (size_t)k * 5;
            #pragma unroll
            for (int q = 0; q < 5; ++q) gout[q] = g_dets[bb][cc][tt][q];
        }
        if (k == 0 && out_size >= BATCH * NP * 5 + BATCH)
            out[BATCH * NP * 5 + bb] = (float)n;
    }

    const int base = BATCH * NP * 5 + BATCH;
    for (int i = base + tid; i < out_size; i += NT) out[i] = 0.0f;

    __syncthreads();
    if (tid == 0) g_done = 0;   // reset for next graph replay
}

extern "C" void kernel_launch(void* const* d_in, const int* in_sizes, int n_in,
                              void* d_out, int out_size)
{
    const float* cls_prob  = (const float*)d_in[0];
    const float* rois      = (const float*)d_in[1];
    const float* bbox_pred = (const float*)d_in[2];
    const float* im_info   = (const float*)d_in[3];
    const float* thr       = (const float*)d_in[4];
    float* out = (float*)d_out;

    const int R = in_sizes[0] / (BATCH * CNUM);      // 1000

    dim3 grid(NCLS / 2, BATCH);                      // 40 x 2 = 80 CTAs
    fused_kernel<<<grid, NT>>>(cls_prob, rois, bbox_pred, im_info, thr,
                               out, out_size, R);
}